// round 14
// baseline (speedup 1.0000x reference)
#include <cuda_runtime.h>
#include <cuda_fp16.h>
#include <cstdint>

#define B_SZ    2
#define S_LEN   2048
#define D_MODEL 1024
#define NHEADS  16
#define DK      64
#define M_ROWS  (B_SZ * S_LEN)     // 4096
#define QKV_N   (3 * D_MODEL)      // 3072

// Scratch (alloc-free: __device__ globals), all fp16 operands
__device__ __half g_qkv[(size_t)M_ROWS * QKV_N];     // qkv (token-major)
__device__ __half g_ctx[(size_t)M_ROWS * D_MODEL];   // ctx head-interleaved
__device__ __half g_xh [(size_t)M_ROWS * D_MODEL];   // x -> half
__device__ __half g_wqt[(size_t)QKV_N * D_MODEL];    // W_qkv^T [N][K] half
__device__ __half g_wot[(size_t)D_MODEL * D_MODEL];  // W_o^T  [N][K] half

// ---------------------------------------------------------------------------
// helpers
// ---------------------------------------------------------------------------
__device__ __forceinline__ uint32_t smem_u32(const void* p) {
    uint32_t a;
    asm("{ .reg .u64 t; cvta.to.shared.u64 t, %1; cvt.u32.u64 %0, t; }"
        : "=r"(a) : "l"(p));
    return a;
}

#define CP_ASYNC16(dst, src) \
    asm volatile("cp.async.cg.shared.global [%0], [%1], 16;" :: "r"(dst), "l"(src))
#define CP_COMMIT() asm volatile("cp.async.commit_group;" ::: "memory")
#define CP_WAIT0()  asm volatile("cp.async.wait_group 0;" ::: "memory")
#define CP_WAIT2()  asm volatile("cp.async.wait_group 2;" ::: "memory")

#define LDSM_X4(r0, r1, r2, r3, addr) \
    asm volatile("ldmatrix.sync.aligned.m8n8.x4.shared.b16 {%0,%1,%2,%3}, [%4];" \
                 : "=r"(r0), "=r"(r1), "=r"(r2), "=r"(r3) : "r"(addr))

#define LDSM_X4_T(r0, r1, r2, r3, addr) \
    asm volatile("ldmatrix.sync.aligned.m8n8.x4.trans.shared.b16 {%0,%1,%2,%3}, [%4];" \
                 : "=r"(r0), "=r"(r1), "=r"(r2), "=r"(r3) : "r"(addr))

// D(f32) += A(f16) * B(f16): m16n8k16
__device__ __forceinline__ void mma_f16(float* c, const unsigned* a,
                                        unsigned b0, unsigned b1) {
    asm volatile(
        "mma.sync.aligned.m16n8k16.row.col.f32.f16.f16.f32 "
        "{%0,%1,%2,%3}, {%4,%5,%6,%7}, {%8,%9}, {%0,%1,%2,%3};\n"
        : "+f"(c[0]), "+f"(c[1]), "+f"(c[2]), "+f"(c[3])
        : "r"(a[0]), "r"(a[1]), "r"(a[2]), "r"(a[3]), "r"(b0), "r"(b1));
}

__device__ __forceinline__ unsigned h2u(__half2 h) {
    return *reinterpret_cast<unsigned*>(&h);
}

// ---------------------------------------------------------------------------
// prep kernels
// ---------------------------------------------------------------------------
__global__ void __launch_bounds__(256)
k_h4(const float* __restrict__ in, __half* __restrict__ out, int n4)
{
    int i = blockIdx.x * 256 + threadIdx.x;
    if (i < n4) {
        float4 v = ((const float4*)in)[i];
        ((__half2*)out)[2 * i]     = __floats2half2_rn(v.x, v.y);
        ((__half2*)out)[2 * i + 1] = __floats2half2_rn(v.z, v.w);
    }
}

// transpose+convert: in f32 [R][C] -> out half [C][R]
__global__ void __launch_bounds__(256)
k_trT(const float* __restrict__ in, __half* __restrict__ out, int R, int C)
{
    __shared__ float tile[32][33];
    const int tx = threadIdx.x, ty = threadIdx.y;
    const int c0 = blockIdx.x * 32, r0 = blockIdx.y * 32;
    #pragma unroll
    for (int i = 0; i < 32; i += 8)
        tile[ty + i][tx] = in[(size_t)(r0 + ty + i) * C + c0 + tx];
    __syncthreads();
    #pragma unroll
    for (int i = 0; i < 32; i += 8)
        out[(size_t)(c0 + ty + i) * R + r0 + tx] = __float2half_rn(tile[tx][ty + i]);
}

// ---------------------------------------------------------------------------
// FP16 GEMM: C[M,N] = A[M,K] @ BT[N,K]^T + bias[N]
// CTA tile 128x128, BK=32, 4-stage cp.async (wait_group 2), 128 threads =
// 4 warps in 2M x 2N layout, warp tile 64x64 (8 LDSM per 32 HMMA: 1.5x less
// smem traffic than 32x64 -> crossbar no longer co-bottleneck). 2 CTAs/SM.
// Issue placement: after compute (round-11; early-issue measured worse).
// ---------------------------------------------------------------------------
#define HS 40
#define STG_H (128 * HS)                 // halfs per operand per stage: 5120
#define ABUF(s) ((s) * 2 * STG_H)
#define BBUF(s) ((s) * 2 * STG_H + STG_H)
#define GT_SMEM (4 * 2 * STG_H * 2)      // 81920 B

template <bool HALF_OUT>
__global__ void __launch_bounds__(128, 2)
k_gemm(const __half* __restrict__ A, const __half* __restrict__ BT,
       const float* __restrict__ bias, void* __restrict__ Cv,
       int N, int K)
{
    extern __shared__ __half smh[];
    const uint32_t sb = smem_u32(smh);
    const int tid  = threadIdx.x;
    const int wid  = tid >> 5;
    const int lane = tid & 31;
    const int lr   = lane >> 2;
    const int lc   = lane & 3;
    const int wm   = (wid & 1) * 64;
    const int wn   = (wid >> 1) * 64;
    const int bm   = blockIdx.y * 128;
    const int bn   = blockIdx.x * 128;

    float acc[4][8][4];
    #pragma unroll
    for (int i = 0; i < 4; i++)
        #pragma unroll
        for (int j = 0; j < 8; j++)
            #pragma unroll
            for (int q = 0; q < 4; q++) acc[i][j][q] = 0.f;

    // cp.async: 512 16B-chunks per operand per stage -> 4 per thread each
    // thread tid owns row tid of both tiles (BK=32 halfs = 4 chunks)
    auto issue = [&](int t) {
        const int s  = t & 3;
        const int k0 = t * 32;
        const __half* ap = A  + (size_t)(bm + tid) * K + k0;
        const __half* bp = BT + (size_t)(bn + tid) * K + k0;
        const uint32_t da = sb + (ABUF(s) + tid * HS) * 2;
        const uint32_t db = sb + (BBUF(s) + tid * HS) * 2;
        CP_ASYNC16(da,      ap);
        CP_ASYNC16(da + 16, ap + 8);
        CP_ASYNC16(da + 32, ap + 16);
        CP_ASYNC16(da + 48, ap + 24);
        CP_ASYNC16(db,      bp);
        CP_ASYNC16(db + 16, bp + 8);
        CP_ASYNC16(db + 32, bp + 16);
        CP_ASYNC16(db + 48, bp + 24);
    };

    const int lane16 = lane & 15;
    const int lhi    = (lane >> 4) * 8;    // +8 halfs for second k-chunk

    const int nT = K / 32;
    issue(0); CP_COMMIT();
    issue(1); CP_COMMIT();
    issue(2); CP_COMMIT();

    for (int t = 0; t < nT; t++) {
        CP_WAIT2();
        __syncthreads();
        const int s = t & 3;
        const uint32_t aBase = sb + ABUF(s) * 2;
        const uint32_t bBase = sb + BBUF(s) * 2;

        #pragma unroll
        for (int kk = 0; kk < 2; kk++) {      // two k16 steps
            unsigned af[4][4];
            #pragma unroll
            for (int i = 0; i < 4; i++)
                LDSM_X4(af[i][0], af[i][1], af[i][2], af[i][3],
                        aBase + ((wm + 16 * i + lane16) * HS + lhi + 16 * kk) * 2);
            #pragma unroll
            for (int p = 0; p < 4; p++) {     // 16-n groups
                unsigned bf[4];
                LDSM_X4(bf[0], bf[1], bf[2], bf[3],
                        bBase + ((wn + 16 * p + lane16) * HS + lhi + 16 * kk) * 2);
                #pragma unroll
                for (int i = 0; i < 4; i++) {
                    mma_f16(acc[i][2 * p],     af[i], bf[0], bf[2]);
                    mma_f16(acc[i][2 * p + 1], af[i], bf[1], bf[3]);
                }
            }
        }
        // stage (t+3)&3 == (t-1)&3 freed by the barrier at top of this iter
        if (t + 3 < nT) issue(t + 3);
        CP_COMMIT();
    }

    #pragma unroll
    for (int j = 0; j < 8; j++) {
        const int col = bn + wn + 8 * j + 2 * lc;
        const float bs0 = bias[col], bs1 = bias[col + 1];
        #pragma unroll
        for (int i = 0; i < 4; i++) {
            const int row = bm + wm + 16 * i + lr;
            if (HALF_OUT) {
                __half* Ch = (__half*)Cv;
                *(__half2*)(Ch + (size_t)row * N + col) =
                    __floats2half2_rn(acc[i][j][0] + bs0, acc[i][j][1] + bs1);
                *(__half2*)(Ch + (size_t)(row + 8) * N + col) =
                    __floats2half2_rn(acc[i][j][2] + bs0, acc[i][j][3] + bs1);
            } else {
                float* Cf = (float*)Cv;
                *(float2*)(Cf + (size_t)row * N + col) =
                    make_float2(acc[i][j][0] + bs0, acc[i][j][1] + bs1);
                *(float2*)(Cf + (size_t)(row + 8) * N + col) =
                    make_float2(acc[i][j][2] + bs0, acc[i][j][3] + bs1);
            }
        }
    }
}

// ---------------------------------------------------------------------------
// FP16 flash attention: 256 threads (8 warps) = 128 q-rows, 64-key tiles.
// 2-stage cp.async, 2 CTAs/SM. mma m16n8k16. P register-resident.
// V loaded token-major; PV B-fragments via ldmatrix.x4.trans (bit-identical
// to the old V^T path). Unchanged from round 13.
// ---------------------------------------------------------------------------
#define AHS 72
#define KSTG (64 * AHS)                            // 4608 halfs
#define KOFF(s) ((s) * 2 * KSTG)
#define VOFF(s) ((s) * 2 * KSTG + KSTG)
#define AT_SMEM (2 * 2 * KSTG * 2)                 // 36864 B

__global__ void __launch_bounds__(256, 2)
k_attn()
{
    extern __shared__ __half smh[];
    const uint32_t sb = smem_u32(smh);
    const int tid  = threadIdx.x;
    const int wid  = tid >> 5;
    const int lane = tid & 31;
    const int lr   = lane >> 2;
    const int lc   = lane & 3;
    const int bh   = blockIdx.x;
    const int b    = bh >> 4;
    const int h    = bh & 15;
    const int q0   = blockIdx.y * 128;

    const __half* base = g_qkv + (size_t)b * S_LEN * QKV_N;
    const int ho = h * (3 * DK);

    // Q fragments from gmem, x0.125 (exact pow2 in fp16)
    unsigned Qf[4][4];
    {
        const __half2 scl = __float2half2_rn(0.125f);
        const __half* qr0 = base + (size_t)(q0 + wid * 16 + lr) * QKV_N + ho;
        const __half* qr1 = qr0 + (size_t)8 * QKV_N;
        #pragma unroll
        for (int kk = 0; kk < 4; kk++) {
            Qf[kk][0] = h2u(__hmul2(*(const __half2*)(qr0 + 16 * kk + 2 * lc), scl));
            Qf[kk][1] = h2u(__hmul2(*(const __half2*)(qr1 + 16 * kk + 2 * lc), scl));
            Qf[kk][2] = h2u(__hmul2(*(const __half2*)(qr0 + 16 * kk + 2 * lc + 8), scl));
            Qf[kk][3] = h2u(__hmul2(*(const __half2*)(qr1 + 16 * kk + 2 * lc + 8), scl));
        }
    }

    // cp.async: K and V each 64 rows (keys) x 8 chunks; 2 chunks/thread each.
    auto issue = [&](int t) {
        const int s  = t & 1;
        const int r  = tid >> 2;            // key row 0..63
        const int cb = (tid & 3) * 16;      // half col 0/16/32/48
        const __half* kp = base + (size_t)(t * 64 + r) * QKV_N + ho + DK + cb;
        const uint32_t dk_ = sb + (KOFF(s) + r * AHS + cb) * 2;
        CP_ASYNC16(dk_,      kp);
        CP_ASYNC16(dk_ + 16, kp + 8);
        const uint32_t dv = sb + (VOFF(s) + r * AHS + cb) * 2;
        CP_ASYNC16(dv,      kp + DK);
        CP_ASYNC16(dv + 16, kp + DK + 8);
    };

    float oAcc[8][4];
    #pragma unroll
    for (int j = 0; j < 8; j++)
        #pragma unroll
        for (int q = 0; q < 4; q++) oAcc[j][q] = 0.f;
    float m0 = -1e30f, m1 = -1e30f, l0 = 0.f, l1 = 0.f;

    const int lane16 = lane & 15;
    const int lhi    = (lane >> 4) * 8;
    const int vrow = (lane & 7) + ((lane >> 4) << 3);
    const int vcol = ((lane >> 3) & 1) << 3;

    const int nT = S_LEN / 64;
    issue(0); CP_COMMIT();

    for (int t = 0; t < nT; t++) {
        CP_WAIT0();
        __syncthreads();
        if (t + 1 < nT) issue(t + 1);
        CP_COMMIT();

        const int s = t & 1;
        const uint32_t kBase = sb + KOFF(s) * 2;
        const uint32_t vBase = sb + VOFF(s) * 2;

        // S = Q @ K^T  (16 q x 64 keys per warp)
        float sAcc[8][4];
        #pragma unroll
        for (int j = 0; j < 8; j++)
            sAcc[j][0] = sAcc[j][1] = sAcc[j][2] = sAcc[j][3] = 0.f;
        #pragma unroll
        for (int kk = 0; kk < 4; kk++) {
            #pragma unroll
            for (int p = 0; p < 4; p++) {
                unsigned bf[4];
                LDSM_X4(bf[0], bf[1], bf[2], bf[3],
                        kBase + ((16 * p + lane16) * AHS + lhi + 16 * kk) * 2);
                mma_f16(sAcc[2 * p],     Qf[kk], bf[0], bf[2]);
                mma_f16(sAcc[2 * p + 1], Qf[kk], bf[1], bf[3]);
            }
        }

        // online softmax (rows lr and lr+8)
        float mx0 = -1e30f, mx1 = -1e30f;
        #pragma unroll
        for (int j = 0; j < 8; j++) {
            mx0 = fmaxf(mx0, fmaxf(sAcc[j][0], sAcc[j][1]));
            mx1 = fmaxf(mx1, fmaxf(sAcc[j][2], sAcc[j][3]));
        }
        mx0 = fmaxf(mx0, __shfl_xor_sync(0xffffffffu, mx0, 1));
        mx0 = fmaxf(mx0, __shfl_xor_sync(0xffffffffu, mx0, 2));
        mx1 = fmaxf(mx1, __shfl_xor_sync(0xffffffffu, mx1, 1));
        mx1 = fmaxf(mx1, __shfl_xor_sync(0xffffffffu, mx1, 2));

        const float mn0 = fmaxf(m0, mx0), mn1 = fmaxf(m1, mx1);
        const float cor0 = __expf(m0 - mn0), cor1 = __expf(m1 - mn1);
        m0 = mn0; m1 = mn1;

        float s0 = 0.f, s1 = 0.f;
        #pragma unroll
        for (int j = 0; j < 8; j++) {
            sAcc[j][0] = __expf(sAcc[j][0] - mn0); s0 += sAcc[j][0];
            sAcc[j][1] = __expf(sAcc[j][1] - mn0); s0 += sAcc[j][1];
            sAcc[j][2] = __expf(sAcc[j][2] - mn1); s1 += sAcc[j][2];
            sAcc[j][3] = __expf(sAcc[j][3] - mn1); s1 += sAcc[j][3];
        }
        s0 += __shfl_xor_sync(0xffffffffu, s0, 1);
        s0 += __shfl_xor_sync(0xffffffffu, s0, 2);
        s1 += __shfl_xor_sync(0xffffffffu, s1, 1);
        s1 += __shfl_xor_sync(0xffffffffu, s1, 2);
        l0 = l0 * cor0 + s0;
        l1 = l1 * cor1 + s1;

        #pragma unroll
        for (int j = 0; j < 8; j++) {
            oAcc[j][0] *= cor0; oAcc[j][1] *= cor0;
            oAcc[j][2] *= cor1; oAcc[j][3] *= cor1;
        }

        // O += P @ V: P A-frags from sAcc registers; V B-frags via x4.trans
        #pragma unroll
        for (int kk = 0; kk < 4; kk++) {      // 16-key steps
            unsigned pf[4];
            pf[0] = h2u(__floats2half2_rn(sAcc[2 * kk][0],     sAcc[2 * kk][1]));
            pf[1] = h2u(__floats2half2_rn(sAcc[2 * kk][2],     sAcc[2 * kk][3]));
            pf[2] = h2u(__floats2half2_rn(sAcc[2 * kk + 1][0], sAcc[2 * kk + 1][1]));
            pf[3] = h2u(__floats2half2_rn(sAcc[2 * kk + 1][2], sAcc[2 * kk + 1][3]));
            #pragma unroll
            for (int p = 0; p < 4; p++) {     // 16-d groups
                unsigned bf[4];
                LDSM_X4_T(bf[0], bf[1], bf[2], bf[3],
                          vBase + ((16 * kk + vrow) * AHS + 16 * p + vcol) * 2);
                mma_f16(oAcc[2 * p],     pf, bf[0], bf[2]);
                mma_f16(oAcc[2 * p + 1], pf, bf[1], bf[3]);
            }
        }
    }

    // epilogue: normalize, convert half, store head-interleaved ctx
    const float inv0 = 1.f / l0, inv1 = 1.f / l1;
    __half* orow0 = g_ctx + (size_t)(b * S_LEN + q0 + wid * 16 + lr) * D_MODEL + h * DK;
    __half* orow1 = orow0 + (size_t)8 * D_MODEL;
    #pragma unroll
    for (int j = 0; j < 8; j++) {
        const int colo = 8 * j + 2 * lc;
        *(__half2*)(orow0 + colo) =
            __floats2half2_rn(oAcc[j][0] * inv0, oAcc[j][1] * inv0);
        *(__half2*)(orow1 + colo) =
            __floats2half2_rn(oAcc[j][2] * inv1, oAcc[j][3] * inv1);
    }
}

// ---------------------------------------------------------------------------
extern "C" void kernel_launch(void* const* d_in, const int* in_sizes, int n_in,
                              void* d_out, int out_size)
{
    (void)in_sizes; (void)n_in; (void)out_size;
    const float* x     = (const float*)d_in[0];
    const float* W_qkv = (const float*)d_in[1];
    const float* b_qkv = (const float*)d_in[2];
    const float* W_o   = (const float*)d_in[3];
    const float* b_o   = (const float*)d_in[4];
    float* out = (float*)d_out;

    static __half *p_qkv = nullptr, *p_ctx, *p_xh, *p_wqt, *p_wot;
    if (!p_qkv) {
        cudaGetSymbolAddress((void**)&p_qkv, g_qkv);
        cudaGetSymbolAddress((void**)&p_ctx, g_ctx);
        cudaGetSymbolAddress((void**)&p_xh,  g_xh);
        cudaGetSymbolAddress((void**)&p_wqt, g_wqt);
        cudaGetSymbolAddress((void**)&p_wot, g_wot);
        cudaFuncSetAttribute(k_gemm<true>,
                             cudaFuncAttributeMaxDynamicSharedMemorySize, GT_SMEM);
        cudaFuncSetAttribute(k_gemm<false>,
                             cudaFuncAttributeMaxDynamicSharedMemorySize, GT_SMEM);
        cudaFuncSetAttribute(k_attn,
                             cudaFuncAttributeMaxDynamicSharedMemorySize, AT_SMEM);
    }

    // prep: x -> half; weights -> transposed half
    k_h4<<<(M_ROWS * D_MODEL / 4 + 255) / 256, 256>>>(x, p_xh, M_ROWS * D_MODEL / 4);
    k_trT<<<dim3(QKV_N / 32, D_MODEL / 32), dim3(32, 8)>>>(W_qkv, p_wqt, D_MODEL, QKV_N);
    k_trT<<<dim3(D_MODEL / 32, D_MODEL / 32), dim3(32, 8)>>>(W_o, p_wot, D_MODEL, D_MODEL);

    k_gemm<true><<<dim3(QKV_N / 128, M_ROWS / 128), 128, GT_SMEM>>>(
        p_xh, p_wqt, b_qkv, p_qkv, QKV_N, D_MODEL);
    k_attn<<<dim3(B_SZ * NHEADS, S_LEN / 128), 256, AT_SMEM>>>();
    k_gemm<false><<<dim3(D_MODEL / 128, M_ROWS / 128), 128, GT_SMEM>>>(
        p_ctx, p_wot, b_o, out, D_MODEL, D_MODEL);
}

// round 15
// speedup vs baseline: 1.2040x; 1.2040x over previous
#include <cuda_runtime.h>
#include <cuda_fp16.h>
#include <cstdint>

#define B_SZ    2
#define S_LEN   2048
#define D_MODEL 1024
#define NHEADS  16
#define DK      64
#define M_ROWS  (B_SZ * S_LEN)     // 4096
#define QKV_N   (3 * D_MODEL)      // 3072

// Scratch (alloc-free: __device__ globals), all fp16 operands
__device__ __half g_qkv[(size_t)M_ROWS * QKV_N];     // qkv (token-major)
__device__ __half g_ctx[(size_t)M_ROWS * D_MODEL];   // ctx head-interleaved
__device__ __half g_xh [(size_t)M_ROWS * D_MODEL];   // x -> half
__device__ __half g_wqt[(size_t)QKV_N * D_MODEL];    // W_qkv^T [N][K] half
__device__ __half g_wot[(size_t)D_MODEL * D_MODEL];  // W_o^T  [N][K] half

// ---------------------------------------------------------------------------
// helpers
// ---------------------------------------------------------------------------
__device__ __forceinline__ uint32_t smem_u32(const void* p) {
    uint32_t a;
    asm("{ .reg .u64 t; cvta.to.shared.u64 t, %1; cvt.u32.u64 %0, t; }"
        : "=r"(a) : "l"(p));
    return a;
}

#define CP_ASYNC16(dst, src) \
    asm volatile("cp.async.cg.shared.global [%0], [%1], 16;" :: "r"(dst), "l"(src))
#define CP_COMMIT() asm volatile("cp.async.commit_group;" ::: "memory")
#define CP_WAIT0()  asm volatile("cp.async.wait_group 0;" ::: "memory")
#define CP_WAIT2()  asm volatile("cp.async.wait_group 2;" ::: "memory")

#define LDSM_X4(r0, r1, r2, r3, addr) \
    asm volatile("ldmatrix.sync.aligned.m8n8.x4.shared.b16 {%0,%1,%2,%3}, [%4];" \
                 : "=r"(r0), "=r"(r1), "=r"(r2), "=r"(r3) : "r"(addr))

#define LDSM_X4_T(r0, r1, r2, r3, addr) \
    asm volatile("ldmatrix.sync.aligned.m8n8.x4.trans.shared.b16 {%0,%1,%2,%3}, [%4];" \
                 : "=r"(r0), "=r"(r1), "=r"(r2), "=r"(r3) : "r"(addr))

// D(f32) += A(f16) * B(f16): m16n8k16
__device__ __forceinline__ void mma_f16(float* c, const unsigned* a,
                                        unsigned b0, unsigned b1) {
    asm volatile(
        "mma.sync.aligned.m16n8k16.row.col.f32.f16.f16.f32 "
        "{%0,%1,%2,%3}, {%4,%5,%6,%7}, {%8,%9}, {%0,%1,%2,%3};\n"
        : "+f"(c[0]), "+f"(c[1]), "+f"(c[2]), "+f"(c[3])
        : "r"(a[0]), "r"(a[1]), "r"(a[2]), "r"(a[3]), "r"(b0), "r"(b1));
}

__device__ __forceinline__ unsigned h2u(__half2 h) {
    return *reinterpret_cast<unsigned*>(&h);
}

// ---------------------------------------------------------------------------
// prep kernels
// ---------------------------------------------------------------------------
__global__ void __launch_bounds__(256)
k_h4(const float* __restrict__ in, __half* __restrict__ out, int n4)
{
    int i = blockIdx.x * 256 + threadIdx.x;
    if (i < n4) {
        float4 v = ((const float4*)in)[i];
        ((__half2*)out)[2 * i]     = __floats2half2_rn(v.x, v.y);
        ((__half2*)out)[2 * i + 1] = __floats2half2_rn(v.z, v.w);
    }
}

// transpose+convert: in f32 [R][C] -> out half [C][R]
__global__ void __launch_bounds__(256)
k_trT(const float* __restrict__ in, __half* __restrict__ out, int R, int C)
{
    __shared__ float tile[32][33];
    const int tx = threadIdx.x, ty = threadIdx.y;
    const int c0 = blockIdx.x * 32, r0 = blockIdx.y * 32;
    #pragma unroll
    for (int i = 0; i < 32; i += 8)
        tile[ty + i][tx] = in[(size_t)(r0 + ty + i) * C + c0 + tx];
    __syncthreads();
    #pragma unroll
    for (int i = 0; i < 32; i += 8)
        out[(size_t)(c0 + ty + i) * R + r0 + tx] = __float2half_rn(tile[tx][ty + i]);
}

// ---------------------------------------------------------------------------
// FP16 GEMM: C[M,N] = A[M,K] @ BT[N,K]^T + bias[N]
// Round-11 measured-best config: Block 128x128, BK=32, 4-stage cp.async,
// wait_group 2, 256 threads = 8 warps (4M x 2N), warp tile 32x64,
// mma m16n8k16, 2 CTAs/SM, stride 40 halfs, issue AFTER compute.
// ---------------------------------------------------------------------------
#define HS 40
#define STG_H (128 * HS)                 // halfs per operand per stage: 5120
#define ABUF(s) ((s) * 2 * STG_H)
#define BBUF(s) ((s) * 2 * STG_H + STG_H)
#define GT_SMEM (4 * 2 * STG_H * 2)      // 81920 B

template <bool HALF_OUT>
__global__ void __launch_bounds__(256, 2)
k_gemm(const __half* __restrict__ A, const __half* __restrict__ BT,
       const float* __restrict__ bias, void* __restrict__ Cv,
       int N, int K)
{
    extern __shared__ __half smh[];
    const uint32_t sb = smem_u32(smh);
    const int tid  = threadIdx.x;
    const int wid  = tid >> 5;
    const int lane = tid & 31;
    const int lr   = lane >> 2;
    const int lc   = lane & 3;
    const int wm   = (wid & 3) * 32;
    const int wn   = (wid >> 2) * 64;
    const int bm   = blockIdx.y * 128;
    const int bn   = blockIdx.x * 128;

    float acc[2][8][4];
    #pragma unroll
    for (int i = 0; i < 2; i++)
        #pragma unroll
        for (int j = 0; j < 8; j++)
            #pragma unroll
            for (int q = 0; q < 4; q++) acc[i][j][q] = 0.f;

    // cp.async: 512 16B-chunks per operand per stage -> 2 per thread each
    const int ldRow = tid >> 1;            // 0..127
    const int ldCol = (tid & 1) * 16;      // half col 0 or 16

    auto issue = [&](int t) {
        const int s  = t & 3;
        const int k0 = t * 32;
        const __half* ap = A  + (size_t)(bm + ldRow) * K + k0 + ldCol;
        const __half* bp = BT + (size_t)(bn + ldRow) * K + k0 + ldCol;
        const uint32_t da = sb + (ABUF(s) + ldRow * HS + ldCol) * 2;
        const uint32_t db = sb + (BBUF(s) + ldRow * HS + ldCol) * 2;
        CP_ASYNC16(da,      ap);
        CP_ASYNC16(da + 16, ap + 8);
        CP_ASYNC16(db,      bp);
        CP_ASYNC16(db + 16, bp + 8);
    };

    const int lane16 = lane & 15;
    const int lhi    = (lane >> 4) * 8;    // +8 halfs for second k-chunk

    const int nT = K / 32;
    issue(0); CP_COMMIT();
    issue(1); CP_COMMIT();
    issue(2); CP_COMMIT();

    for (int t = 0; t < nT; t++) {
        CP_WAIT2();
        __syncthreads();
        const int s = t & 3;
        const uint32_t aBase = sb + ABUF(s) * 2;
        const uint32_t bBase = sb + BBUF(s) * 2;

        #pragma unroll
        for (int kk = 0; kk < 2; kk++) {      // two k16 steps
            unsigned af0[4], af1[4];
            LDSM_X4(af0[0], af0[1], af0[2], af0[3],
                    aBase + ((wm + lane16) * HS + lhi + 16 * kk) * 2);
            LDSM_X4(af1[0], af1[1], af1[2], af1[3],
                    aBase + ((wm + 16 + lane16) * HS + lhi + 16 * kk) * 2);
            #pragma unroll
            for (int p = 0; p < 4; p++) {     // 16-n groups
                unsigned bf[4];
                LDSM_X4(bf[0], bf[1], bf[2], bf[3],
                        bBase + ((wn + 16 * p + lane16) * HS + lhi + 16 * kk) * 2);
                mma_f16(acc[0][2 * p],     af0, bf[0], bf[2]);
                mma_f16(acc[1][2 * p],     af1, bf[0], bf[2]);
                mma_f16(acc[0][2 * p + 1], af0, bf[1], bf[3]);
                mma_f16(acc[1][2 * p + 1], af1, bf[1], bf[3]);
            }
        }
        if (t + 3 < nT) issue(t + 3);
        CP_COMMIT();
    }

    #pragma unroll
    for (int j = 0; j < 8; j++) {
        const int col = bn + wn + 8 * j + 2 * lc;
        const float bs0 = bias[col], bs1 = bias[col + 1];
        #pragma unroll
        for (int i = 0; i < 2; i++) {
            const int row = bm + wm + 16 * i + lr;
            if (HALF_OUT) {
                __half* Ch = (__half*)Cv;
                *(__half2*)(Ch + (size_t)row * N + col) =
                    __floats2half2_rn(acc[i][j][0] + bs0, acc[i][j][1] + bs1);
                *(__half2*)(Ch + (size_t)(row + 8) * N + col) =
                    __floats2half2_rn(acc[i][j][2] + bs0, acc[i][j][3] + bs1);
            } else {
                float* Cf = (float*)Cv;
                *(float2*)(Cf + (size_t)row * N + col) =
                    make_float2(acc[i][j][0] + bs0, acc[i][j][1] + bs1);
                *(float2*)(Cf + (size_t)(row + 8) * N + col) =
                    make_float2(acc[i][j][2] + bs0, acc[i][j][3] + bs1);
            }
        }
    }
}

// ---------------------------------------------------------------------------
// FP16 flash attention (round-13 version): 256 threads (8 warps) = 128 q-rows,
// 64-key tiles, 2-stage cp.async, 2 CTAs/SM, mma m16n8k16.
// P register-resident; V token-major with PV B-fragments via ldmatrix.x4.trans.
// ---------------------------------------------------------------------------
#define AHS 72
#define KSTG (64 * AHS)                            // 4608 halfs
#define KOFF(s) ((s) * 2 * KSTG)
#define VOFF(s) ((s) * 2 * KSTG + KSTG)
#define AT_SMEM (2 * 2 * KSTG * 2)                 // 36864 B

__global__ void __launch_bounds__(256, 2)
k_attn()
{
    extern __shared__ __half smh[];
    const uint32_t sb = smem_u32(smh);
    const int tid  = threadIdx.x;
    const int wid  = tid >> 5;
    const int lane = tid & 31;
    const int lr   = lane >> 2;
    const int lc   = lane & 3;
    const int bh   = blockIdx.x;
    const int b    = bh >> 4;
    const int h    = bh & 15;
    const int q0   = blockIdx.y * 128;

    const __half* base = g_qkv + (size_t)b * S_LEN * QKV_N;
    const int ho = h * (3 * DK);

    // Q fragments from gmem, x0.125 (exact pow2 in fp16)
    unsigned Qf[4][4];
    {
        const __half2 scl = __float2half2_rn(0.125f);
        const __half* qr0 = base + (size_t)(q0 + wid * 16 + lr) * QKV_N + ho;
        const __half* qr1 = qr0 + (size_t)8 * QKV_N;
        #pragma unroll
        for (int kk = 0; kk < 4; kk++) {
            Qf[kk][0] = h2u(__hmul2(*(const __half2*)(qr0 + 16 * kk + 2 * lc), scl));
            Qf[kk][1] = h2u(__hmul2(*(const __half2*)(qr1 + 16 * kk + 2 * lc), scl));
            Qf[kk][2] = h2u(__hmul2(*(const __half2*)(qr0 + 16 * kk + 2 * lc + 8), scl));
            Qf[kk][3] = h2u(__hmul2(*(const __half2*)(qr1 + 16 * kk + 2 * lc + 8), scl));
        }
    }

    // cp.async: K and V each 64 rows (keys) x 8 chunks; 2 chunks/thread each.
    auto issue = [&](int t) {
        const int s  = t & 1;
        const int r  = tid >> 2;            // key row 0..63
        const int cb = (tid & 3) * 16;      // half col 0/16/32/48
        const __half* kp = base + (size_t)(t * 64 + r) * QKV_N + ho + DK + cb;
        const uint32_t dk_ = sb + (KOFF(s) + r * AHS + cb) * 2;
        CP_ASYNC16(dk_,      kp);
        CP_ASYNC16(dk_ + 16, kp + 8);
        const uint32_t dv = sb + (VOFF(s) + r * AHS + cb) * 2;
        CP_ASYNC16(dv,      kp + DK);
        CP_ASYNC16(dv + 16, kp + DK + 8);
    };

    float oAcc[8][4];
    #pragma unroll
    for (int j = 0; j < 8; j++)
        #pragma unroll
        for (int q = 0; q < 4; q++) oAcc[j][q] = 0.f;
    float m0 = -1e30f, m1 = -1e30f, l0 = 0.f, l1 = 0.f;

    const int lane16 = lane & 15;
    const int lhi    = (lane >> 4) * 8;
    const int vrow = (lane & 7) + ((lane >> 4) << 3);
    const int vcol = ((lane >> 3) & 1) << 3;

    const int nT = S_LEN / 64;
    issue(0); CP_COMMIT();

    for (int t = 0; t < nT; t++) {
        CP_WAIT0();
        __syncthreads();
        if (t + 1 < nT) issue(t + 1);
        CP_COMMIT();

        const int s = t & 1;
        const uint32_t kBase = sb + KOFF(s) * 2;
        const uint32_t vBase = sb + VOFF(s) * 2;

        // S = Q @ K^T  (16 q x 64 keys per warp)
        float sAcc[8][4];
        #pragma unroll
        for (int j = 0; j < 8; j++)
            sAcc[j][0] = sAcc[j][1] = sAcc[j][2] = sAcc[j][3] = 0.f;
        #pragma unroll
        for (int kk = 0; kk < 4; kk++) {
            #pragma unroll
            for (int p = 0; p < 4; p++) {
                unsigned bf[4];
                LDSM_X4(bf[0], bf[1], bf[2], bf[3],
                        kBase + ((16 * p + lane16) * AHS + lhi + 16 * kk) * 2);
                mma_f16(sAcc[2 * p],     Qf[kk], bf[0], bf[2]);
                mma_f16(sAcc[2 * p + 1], Qf[kk], bf[1], bf[3]);
            }
        }

        // online softmax (rows lr and lr+8)
        float mx0 = -1e30f, mx1 = -1e30f;
        #pragma unroll
        for (int j = 0; j < 8; j++) {
            mx0 = fmaxf(mx0, fmaxf(sAcc[j][0], sAcc[j][1]));
            mx1 = fmaxf(mx1, fmaxf(sAcc[j][2], sAcc[j][3]));
        }
        mx0 = fmaxf(mx0, __shfl_xor_sync(0xffffffffu, mx0, 1));
        mx0 = fmaxf(mx0, __shfl_xor_sync(0xffffffffu, mx0, 2));
        mx1 = fmaxf(mx1, __shfl_xor_sync(0xffffffffu, mx1, 1));
        mx1 = fmaxf(mx1, __shfl_xor_sync(0xffffffffu, mx1, 2));

        const float mn0 = fmaxf(m0, mx0), mn1 = fmaxf(m1, mx1);
        const float cor0 = __expf(m0 - mn0), cor1 = __expf(m1 - mn1);
        m0 = mn0; m1 = mn1;

        float s0 = 0.f, s1 = 0.f;
        #pragma unroll
        for (int j = 0; j < 8; j++) {
            sAcc[j][0] = __expf(sAcc[j][0] - mn0); s0 += sAcc[j][0];
            sAcc[j][1] = __expf(sAcc[j][1] - mn0); s0 += sAcc[j][1];
            sAcc[j][2] = __expf(sAcc[j][2] - mn1); s1 += sAcc[j][2];
            sAcc[j][3] = __expf(sAcc[j][3] - mn1); s1 += sAcc[j][3];
        }
        s0 += __shfl_xor_sync(0xffffffffu, s0, 1);
        s0 += __shfl_xor_sync(0xffffffffu, s0, 2);
        s1 += __shfl_xor_sync(0xffffffffu, s1, 1);
        s1 += __shfl_xor_sync(0xffffffffu, s1, 2);
        l0 = l0 * cor0 + s0;
        l1 = l1 * cor1 + s1;

        #pragma unroll
        for (int j = 0; j < 8; j++) {
            oAcc[j][0] *= cor0; oAcc[j][1] *= cor0;
            oAcc[j][2] *= cor1; oAcc[j][3] *= cor1;
        }

        // O += P @ V: P A-frags from sAcc registers; V B-frags via x4.trans
        #pragma unroll
        for (int kk = 0; kk < 4; kk++) {      // 16-key steps
            unsigned pf[4];
            pf[0] = h2u(__floats2half2_rn(sAcc[2 * kk][0],     sAcc[2 * kk][1]));
            pf[1] = h2u(__floats2half2_rn(sAcc[2 * kk][2],     sAcc[2 * kk][3]));
            pf[2] = h2u(__floats2half2_rn(sAcc[2 * kk + 1][0], sAcc[2 * kk + 1][1]));
            pf[3] = h2u(__floats2half2_rn(sAcc[2 * kk + 1][2], sAcc[2 * kk + 1][3]));
            #pragma unroll
            for (int p = 0; p < 4; p++) {     // 16-d groups
                unsigned bf[4];
                LDSM_X4_T(bf[0], bf[1], bf[2], bf[3],
                          vBase + ((16 * kk + vrow) * AHS + 16 * p + vcol) * 2);
                mma_f16(oAcc[2 * p],     pf, bf[0], bf[2]);
                mma_f16(oAcc[2 * p + 1], pf, bf[1], bf[3]);
            }
        }
    }

    // epilogue: normalize, convert half, store head-interleaved ctx
    const float inv0 = 1.f / l0, inv1 = 1.f / l1;
    __half* orow0 = g_ctx + (size_t)(b * S_LEN + q0 + wid * 16 + lr) * D_MODEL + h * DK;
    __half* orow1 = orow0 + (size_t)8 * D_MODEL;
    #pragma unroll
    for (int j = 0; j < 8; j++) {
        const int colo = 8 * j + 2 * lc;
        *(__half2*)(orow0 + colo) =
            __floats2half2_rn(oAcc[j][0] * inv0, oAcc[j][1] * inv0);
        *(__half2*)(orow1 + colo) =
            __floats2half2_rn(oAcc[j][2] * inv1, oAcc[j][3] * inv1);
    }
}

// ---------------------------------------------------------------------------
extern "C" void kernel_launch(void* const* d_in, const int* in_sizes, int n_in,
                              void* d_out, int out_size)
{
    (void)in_sizes; (void)n_in; (void)out_size;
    const float* x     = (const float*)d_in[0];
    const float* W_qkv = (const float*)d_in[1];
    const float* b_qkv = (const float*)d_in[2];
    const float* W_o   = (const float*)d_in[3];
    const float* b_o   = (const float*)d_in[4];
    float* out = (float*)d_out;

    static __half *p_qkv = nullptr, *p_ctx, *p_xh, *p_wqt, *p_wot;
    if (!p_qkv) {
        cudaGetSymbolAddress((void**)&p_qkv, g_qkv);
        cudaGetSymbolAddress((void**)&p_ctx, g_ctx);
        cudaGetSymbolAddress((void**)&p_xh,  g_xh);
        cudaGetSymbolAddress((void**)&p_wqt, g_wqt);
        cudaGetSymbolAddress((void**)&p_wot, g_wot);
        cudaFuncSetAttribute(k_gemm<true>,
                             cudaFuncAttributeMaxDynamicSharedMemorySize, GT_SMEM);
        cudaFuncSetAttribute(k_gemm<false>,
                             cudaFuncAttributeMaxDynamicSharedMemorySize, GT_SMEM);
        cudaFuncSetAttribute(k_attn,
                             cudaFuncAttributeMaxDynamicSharedMemorySize, AT_SMEM);
    }

    // prep: x -> half; weights -> transposed half
    k_h4<<<(M_ROWS * D_MODEL / 4 + 255) / 256, 256>>>(x, p_xh, M_ROWS * D_MODEL / 4);
    k_trT<<<dim3(QKV_N / 32, D_MODEL / 32), dim3(32, 8)>>>(W_qkv, p_wqt, D_MODEL, QKV_N);
    k_trT<<<dim3(D_MODEL / 32, D_MODEL / 32), dim3(32, 8)>>>(W_o, p_wot, D_MODEL, D_MODEL);

    k_gemm<true><<<dim3(QKV_N / 128, M_ROWS / 128), 256, GT_SMEM>>>(
        p_xh, p_wqt, b_qkv, p_qkv, QKV_N, D_MODEL);
    k_attn<<<dim3(B_SZ * NHEADS, S_LEN / 128), 256, AT_SMEM>>>();
    k_gemm<false><<<dim3(D_MODEL / 128, M_ROWS / 128), 256, GT_SMEM>>>(
        p_ctx, p_wot, b_o, out, D_MODEL, D_MODEL);
}

// round 16
// speedup vs baseline: 1.2052x; 1.0010x over previous
#include <cuda_runtime.h>
#include <cuda_fp16.h>
#include <cstdint>

#define B_SZ    2
#define S_LEN   2048
#define D_MODEL 1024
#define NHEADS  16
#define DK      64
#define M_ROWS  (B_SZ * S_LEN)     // 4096
#define QKV_N   (3 * D_MODEL)      // 3072

// Scratch (alloc-free: __device__ globals), all fp16 operands
__device__ __half g_qkv[(size_t)M_ROWS * QKV_N];     // qkv (token-major)
__device__ __half g_ctx[(size_t)M_ROWS * D_MODEL];   // ctx head-interleaved
__device__ __half g_xh [(size_t)M_ROWS * D_MODEL];   // x -> half
__device__ __half g_wqt[(size_t)QKV_N * D_MODEL];    // W_qkv^T [N][K] half
__device__ __half g_wot[(size_t)D_MODEL * D_MODEL];  // W_o^T  [N][K] half

// ---------------------------------------------------------------------------
// helpers
// ---------------------------------------------------------------------------
__device__ __forceinline__ uint32_t smem_u32(const void* p) {
    uint32_t a;
    asm("{ .reg .u64 t; cvta.to.shared.u64 t, %1; cvt.u32.u64 %0, t; }"
        : "=r"(a) : "l"(p));
    return a;
}

#define CP_ASYNC16(dst, src) \
    asm volatile("cp.async.cg.shared.global [%0], [%1], 16;" :: "r"(dst), "l"(src))
#define CP_COMMIT() asm volatile("cp.async.commit_group;" ::: "memory")
#define CP_WAIT1()  asm volatile("cp.async.wait_group 1;" ::: "memory")
#define CP_WAIT2()  asm volatile("cp.async.wait_group 2;" ::: "memory")

#define LDSM_X4(r0, r1, r2, r3, addr) \
    asm volatile("ldmatrix.sync.aligned.m8n8.x4.shared.b16 {%0,%1,%2,%3}, [%4];" \
                 : "=r"(r0), "=r"(r1), "=r"(r2), "=r"(r3) : "r"(addr))

#define LDSM_X4_T(r0, r1, r2, r3, addr) \
    asm volatile("ldmatrix.sync.aligned.m8n8.x4.trans.shared.b16 {%0,%1,%2,%3}, [%4];" \
                 : "=r"(r0), "=r"(r1), "=r"(r2), "=r"(r3) : "r"(addr))

// D(f32) += A(f16) * B(f16): m16n8k16
__device__ __forceinline__ void mma_f16(float* c, const unsigned* a,
                                        unsigned b0, unsigned b1) {
    asm volatile(
        "mma.sync.aligned.m16n8k16.row.col.f32.f16.f16.f32 "
        "{%0,%1,%2,%3}, {%4,%5,%6,%7}, {%8,%9}, {%0,%1,%2,%3};\n"
        : "+f"(c[0]), "+f"(c[1]), "+f"(c[2]), "+f"(c[3])
        : "r"(a[0]), "r"(a[1]), "r"(a[2]), "r"(a[3]), "r"(b0), "r"(b1));
}

__device__ __forceinline__ unsigned h2u(__half2 h) {
    return *reinterpret_cast<unsigned*>(&h);
}

// ---------------------------------------------------------------------------
// prep kernels
// ---------------------------------------------------------------------------
__global__ void __launch_bounds__(256)
k_h4(const float* __restrict__ in, __half* __restrict__ out, int n4)
{
    int i = blockIdx.x * 256 + threadIdx.x;
    if (i < n4) {
        float4 v = ((const float4*)in)[i];
        ((__half2*)out)[2 * i]     = __floats2half2_rn(v.x, v.y);
        ((__half2*)out)[2 * i + 1] = __floats2half2_rn(v.z, v.w);
    }
}

// transpose+convert: in f32 [R][C] -> out half [C][R]
__global__ void __launch_bounds__(256)
k_trT(const float* __restrict__ in, __half* __restrict__ out, int R, int C)
{
    __shared__ float tile[32][33];
    const int tx = threadIdx.x, ty = threadIdx.y;
    const int c0 = blockIdx.x * 32, r0 = blockIdx.y * 32;
    #pragma unroll
    for (int i = 0; i < 32; i += 8)
        tile[ty + i][tx] = in[(size_t)(r0 + ty + i) * C + c0 + tx];
    __syncthreads();
    #pragma unroll
    for (int i = 0; i < 32; i += 8)
        out[(size_t)(c0 + ty + i) * R + r0 + tx] = __float2half_rn(tile[tx][ty + i]);
}

// ---------------------------------------------------------------------------
// FP16 GEMM: C[M,N] = A[M,K] @ BT[N,K]^T + bias[N]
// Round-11 measured-best config: Block 128x128, BK=32, 4-stage cp.async,
// wait_group 2, 256 threads = 8 warps (4M x 2N), warp tile 32x64,
// mma m16n8k16, 2 CTAs/SM, stride 40 halfs, issue AFTER compute.
// ---------------------------------------------------------------------------
#define HS 40
#define STG_H (128 * HS)                 // halfs per operand per stage: 5120
#define ABUF(s) ((s) * 2 * STG_H)
#define BBUF(s) ((s) * 2 * STG_H + STG_H)
#define GT_SMEM (4 * 2 * STG_H * 2)      // 81920 B

template <bool HALF_OUT>
__global__ void __launch_bounds__(256, 2)
k_gemm(const __half* __restrict__ A, const __half* __restrict__ BT,
       const float* __restrict__ bias, void* __restrict__ Cv,
       int N, int K)
{
    extern __shared__ __half smh[];
    const uint32_t sb = smem_u32(smh);
    const int tid  = threadIdx.x;
    const int wid  = tid >> 5;
    const int lane = tid & 31;
    const int lr   = lane >> 2;
    const int lc   = lane & 3;
    const int wm   = (wid & 3) * 32;
    const int wn   = (wid >> 2) * 64;
    const int bm   = blockIdx.y * 128;
    const int bn   = blockIdx.x * 128;

    float acc[2][8][4];
    #pragma unroll
    for (int i = 0; i < 2; i++)
        #pragma unroll
        for (int j = 0; j < 8; j++)
            #pragma unroll
            for (int q = 0; q < 4; q++) acc[i][j][q] = 0.f;

    // cp.async: 512 16B-chunks per operand per stage -> 2 per thread each
    const int ldRow = tid >> 1;            // 0..127
    const int ldCol = (tid & 1) * 16;      // half col 0 or 16

    auto issue = [&](int t) {
        const int s  = t & 3;
        const int k0 = t * 32;
        const __half* ap = A  + (size_t)(bm + ldRow) * K + k0 + ldCol;
        const __half* bp = BT + (size_t)(bn + ldRow) * K + k0 + ldCol;
        const uint32_t da = sb + (ABUF(s) + ldRow * HS + ldCol) * 2;
        const uint32_t db = sb + (BBUF(s) + ldRow * HS + ldCol) * 2;
        CP_ASYNC16(da,      ap);
        CP_ASYNC16(da + 16, ap + 8);
        CP_ASYNC16(db,      bp);
        CP_ASYNC16(db + 16, bp + 8);
    };

    const int lane16 = lane & 15;
    const int lhi    = (lane >> 4) * 8;    // +8 halfs for second k-chunk

    const int nT = K / 32;
    issue(0); CP_COMMIT();
    issue(1); CP_COMMIT();
    issue(2); CP_COMMIT();

    for (int t = 0; t < nT; t++) {
        CP_WAIT2();
        __syncthreads();
        const int s = t & 3;
        const uint32_t aBase = sb + ABUF(s) * 2;
        const uint32_t bBase = sb + BBUF(s) * 2;

        #pragma unroll
        for (int kk = 0; kk < 2; kk++) {      // two k16 steps
            unsigned af0[4], af1[4];
            LDSM_X4(af0[0], af0[1], af0[2], af0[3],
                    aBase + ((wm + lane16) * HS + lhi + 16 * kk) * 2);
            LDSM_X4(af1[0], af1[1], af1[2], af1[3],
                    aBase + ((wm + 16 + lane16) * HS + lhi + 16 * kk) * 2);
            #pragma unroll
            for (int p = 0; p < 4; p++) {     // 16-n groups
                unsigned bf[4];
                LDSM_X4(bf[0], bf[1], bf[2], bf[3],
                        bBase + ((wn + 16 * p + lane16) * HS + lhi + 16 * kk) * 2);
                mma_f16(acc[0][2 * p],     af0, bf[0], bf[2]);
                mma_f16(acc[1][2 * p],     af1, bf[0], bf[2]);
                mma_f16(acc[0][2 * p + 1], af0, bf[1], bf[3]);
                mma_f16(acc[1][2 * p + 1], af1, bf[1], bf[3]);
            }
        }
        if (t + 3 < nT) issue(t + 3);
        CP_COMMIT();
    }

    #pragma unroll
    for (int j = 0; j < 8; j++) {
        const int col = bn + wn + 8 * j + 2 * lc;
        const float bs0 = bias[col], bs1 = bias[col + 1];
        #pragma unroll
        for (int i = 0; i < 2; i++) {
            const int row = bm + wm + 16 * i + lr;
            if (HALF_OUT) {
                __half* Ch = (__half*)Cv;
                *(__half2*)(Ch + (size_t)row * N + col) =
                    __floats2half2_rn(acc[i][j][0] + bs0, acc[i][j][1] + bs1);
                *(__half2*)(Ch + (size_t)(row + 8) * N + col) =
                    __floats2half2_rn(acc[i][j][2] + bs0, acc[i][j][3] + bs1);
            } else {
                float* Cf = (float*)Cv;
                *(float2*)(Cf + (size_t)row * N + col) =
                    make_float2(acc[i][j][0] + bs0, acc[i][j][1] + bs1);
                *(float2*)(Cf + (size_t)(row + 8) * N + col) =
                    make_float2(acc[i][j][2] + bs0, acc[i][j][3] + bs1);
            }
        }
    }
}

// ---------------------------------------------------------------------------
// FP16 flash attention: 256 threads (8 warps) = 128 q-rows, 64-key tiles.
// NEW: 3-stage cp.async with wait_group 1 while KEEPING 2 CTAs/SM
// (55.3KB x 2 = 110.6KB smem). issue(t+2) targets stage (t-1)%3, freed by the
// barrier that retired compute(t-1); wait1 leaves group t+1 in flight.
// mma m16n8k16. P register-resident; V token-major, PV B-frags via x4.trans.
// ---------------------------------------------------------------------------
#define AHS 72
#define KSTG (64 * AHS)                            // 4608 halfs
#define KOFF(s) ((s) * 2 * KSTG)
#define VOFF(s) ((s) * 2 * KSTG + KSTG)
#define AT_SMEM (3 * 2 * KSTG * 2)                 // 55296 B

__global__ void __launch_bounds__(256, 2)
k_attn()
{
    extern __shared__ __half smh[];
    const uint32_t sb = smem_u32(smh);
    const int tid  = threadIdx.x;
    const int wid  = tid >> 5;
    const int lane = tid & 31;
    const int lr   = lane >> 2;
    const int lc   = lane & 3;
    const int bh   = blockIdx.x;
    const int b    = bh >> 4;
    const int h    = bh & 15;
    const int q0   = blockIdx.y * 128;

    const __half* base = g_qkv + (size_t)b * S_LEN * QKV_N;
    const int ho = h * (3 * DK);

    // Q fragments from gmem, x0.125 (exact pow2 in fp16)
    unsigned Qf[4][4];
    {
        const __half2 scl = __float2half2_rn(0.125f);
        const __half* qr0 = base + (size_t)(q0 + wid * 16 + lr) * QKV_N + ho;
        const __half* qr1 = qr0 + (size_t)8 * QKV_N;
        #pragma unroll
        for (int kk = 0; kk < 4; kk++) {
            Qf[kk][0] = h2u(__hmul2(*(const __half2*)(qr0 + 16 * kk + 2 * lc), scl));
            Qf[kk][1] = h2u(__hmul2(*(const __half2*)(qr1 + 16 * kk + 2 * lc), scl));
            Qf[kk][2] = h2u(__hmul2(*(const __half2*)(qr0 + 16 * kk + 2 * lc + 8), scl));
            Qf[kk][3] = h2u(__hmul2(*(const __half2*)(qr1 + 16 * kk + 2 * lc + 8), scl));
        }
    }

    // cp.async: K and V each 64 rows (keys) x 8 chunks; 2 chunks/thread each.
    auto issue = [&](int t) {
        const int s  = t % 3;
        const int r  = tid >> 2;            // key row 0..63
        const int cb = (tid & 3) * 16;      // half col 0/16/32/48
        const __half* kp = base + (size_t)(t * 64 + r) * QKV_N + ho + DK + cb;
        const uint32_t dk_ = sb + (KOFF(s) + r * AHS + cb) * 2;
        CP_ASYNC16(dk_,      kp);
        CP_ASYNC16(dk_ + 16, kp + 8);
        const uint32_t dv = sb + (VOFF(s) + r * AHS + cb) * 2;
        CP_ASYNC16(dv,      kp + DK);
        CP_ASYNC16(dv + 16, kp + DK + 8);
    };

    float oAcc[8][4];
    #pragma unroll
    for (int j = 0; j < 8; j++)
        #pragma unroll
        for (int q = 0; q < 4; q++) oAcc[j][q] = 0.f;
    float m0 = -1e30f, m1 = -1e30f, l0 = 0.f, l1 = 0.f;

    const int lane16 = lane & 15;
    const int lhi    = (lane >> 4) * 8;
    const int vrow = (lane & 7) + ((lane >> 4) << 3);
    const int vcol = ((lane >> 3) & 1) << 3;

    const int nT = S_LEN / 64;
    issue(0); CP_COMMIT();
    issue(1); CP_COMMIT();

    for (int t = 0; t < nT; t++) {
        CP_WAIT1();
        __syncthreads();
        // stage (t+2)%3 == (t-1)%3 freed by the barrier above
        if (t + 2 < nT) issue(t + 2);
        CP_COMMIT();

        const int s = t % 3;
        const uint32_t kBase = sb + KOFF(s) * 2;
        const uint32_t vBase = sb + VOFF(s) * 2;

        // S = Q @ K^T  (16 q x 64 keys per warp)
        float sAcc[8][4];
        #pragma unroll
        for (int j = 0; j < 8; j++)
            sAcc[j][0] = sAcc[j][1] = sAcc[j][2] = sAcc[j][3] = 0.f;
        #pragma unroll
        for (int kk = 0; kk < 4; kk++) {
            #pragma unroll
            for (int p = 0; p < 4; p++) {
                unsigned bf[4];
                LDSM_X4(bf[0], bf[1], bf[2], bf[3],
                        kBase + ((16 * p + lane16) * AHS + lhi + 16 * kk) * 2);
                mma_f16(sAcc[2 * p],     Qf[kk], bf[0], bf[2]);
                mma_f16(sAcc[2 * p + 1], Qf[kk], bf[1], bf[3]);
            }
        }

        // online softmax (rows lr and lr+8)
        float mx0 = -1e30f, mx1 = -1e30f;
        #pragma unroll
        for (int j = 0; j < 8; j++) {
            mx0 = fmaxf(mx0, fmaxf(sAcc[j][0], sAcc[j][1]));
            mx1 = fmaxf(mx1, fmaxf(sAcc[j][2], sAcc[j][3]));
        }
        mx0 = fmaxf(mx0, __shfl_xor_sync(0xffffffffu, mx0, 1));
        mx0 = fmaxf(mx0, __shfl_xor_sync(0xffffffffu, mx0, 2));
        mx1 = fmaxf(mx1, __shfl_xor_sync(0xffffffffu, mx1, 1));
        mx1 = fmaxf(mx1, __shfl_xor_sync(0xffffffffu, mx1, 2));

        const float mn0 = fmaxf(m0, mx0), mn1 = fmaxf(m1, mx1);
        const float cor0 = __expf(m0 - mn0), cor1 = __expf(m1 - mn1);
        m0 = mn0; m1 = mn1;

        float s0 = 0.f, s1 = 0.f;
        #pragma unroll
        for (int j = 0; j < 8; j++) {
            sAcc[j][0] = __expf(sAcc[j][0] - mn0); s0 += sAcc[j][0];
            sAcc[j][1] = __expf(sAcc[j][1] - mn0); s0 += sAcc[j][1];
            sAcc[j][2] = __expf(sAcc[j][2] - mn1); s1 += sAcc[j][2];
            sAcc[j][3] = __expf(sAcc[j][3] - mn1); s1 += sAcc[j][3];
        }
        s0 += __shfl_xor_sync(0xffffffffu, s0, 1);
        s0 += __shfl_xor_sync(0xffffffffu, s0, 2);
        s1 += __shfl_xor_sync(0xffffffffu, s1, 1);
        s1 += __shfl_xor_sync(0xffffffffu, s1, 2);
        l0 = l0 * cor0 + s0;
        l1 = l1 * cor1 + s1;

        #pragma unroll
        for (int j = 0; j < 8; j++) {
            oAcc[j][0] *= cor0; oAcc[j][1] *= cor0;
            oAcc[j][2] *= cor1; oAcc[j][3] *= cor1;
        }

        // O += P @ V: P A-frags from sAcc registers; V B-frags via x4.trans
        #pragma unroll
        for (int kk = 0; kk < 4; kk++) {      // 16-key steps
            unsigned pf[4];
            pf[0] = h2u(__floats2half2_rn(sAcc[2 * kk][0],     sAcc[2 * kk][1]));
            pf[1] = h2u(__floats2half2_rn(sAcc[2 * kk][2],     sAcc[2 * kk][3]));
            pf[2] = h2u(__floats2half2_rn(sAcc[2 * kk + 1][0], sAcc[2 * kk + 1][1]));
            pf[3] = h2u(__floats2half2_rn(sAcc[2 * kk + 1][2], sAcc[2 * kk + 1][3]));
            #pragma unroll
            for (int p = 0; p < 4; p++) {     // 16-d groups
                unsigned bf[4];
                LDSM_X4_T(bf[0], bf[1], bf[2], bf[3],
                          vBase + ((16 * kk + vrow) * AHS + 16 * p + vcol) * 2);
                mma_f16(oAcc[2 * p],     pf, bf[0], bf[2]);
                mma_f16(oAcc[2 * p + 1], pf, bf[1], bf[3]);
            }
        }
    }

    // epilogue: normalize, convert half, store head-interleaved ctx
    const float inv0 = 1.f / l0, inv1 = 1.f / l1;
    __half* orow0 = g_ctx + (size_t)(b * S_LEN + q0 + wid * 16 + lr) * D_MODEL + h * DK;
    __half* orow1 = orow0 + (size_t)8 * D_MODEL;
    #pragma unroll
    for (int j = 0; j < 8; j++) {
        const int colo = 8 * j + 2 * lc;
        *(__half2*)(orow0 + colo) =
            __floats2half2_rn(oAcc[j][0] * inv0, oAcc[j][1] * inv0);
        *(__half2*)(orow1 + colo) =
            __floats2half2_rn(oAcc[j][2] * inv1, oAcc[j][3] * inv1);
    }
}

// ---------------------------------------------------------------------------
extern "C" void kernel_launch(void* const* d_in, const int* in_sizes, int n_in,
                              void* d_out, int out_size)
{
    (void)in_sizes; (void)n_in; (void)out_size;
    const float* x     = (const float*)d_in[0];
    const float* W_qkv = (const float*)d_in[1];
    const float* b_qkv = (const float*)d_in[2];
    const float* W_o   = (const float*)d_in[3];
    const float* b_o   = (const float*)d_in[4];
    float* out = (float*)d_out;

    static __half *p_qkv = nullptr, *p_ctx, *p_xh, *p_wqt, *p_wot;
    if (!p_qkv) {
        cudaGetSymbolAddress((void**)&p_qkv, g_qkv);
        cudaGetSymbolAddress((void**)&p_ctx, g_ctx);
        cudaGetSymbolAddress((void**)&p_xh,  g_xh);
        cudaGetSymbolAddress((void**)&p_wqt, g_wqt);
        cudaGetSymbolAddress((void**)&p_wot, g_wot);
        cudaFuncSetAttribute(k_gemm<true>,
                             cudaFuncAttributeMaxDynamicSharedMemorySize, GT_SMEM);
        cudaFuncSetAttribute(k_gemm<false>,
                             cudaFuncAttributeMaxDynamicSharedMemorySize, GT_SMEM);
        cudaFuncSetAttribute(k_attn,
                             cudaFuncAttributeMaxDynamicSharedMemorySize, AT_SMEM);
    }

    // prep: x -> half; weights -> transposed half
    k_h4<<<(M_ROWS * D_MODEL / 4 + 255) / 256, 256>>>(x, p_xh, M_ROWS * D_MODEL / 4);
    k_trT<<<dim3(QKV_N / 32, D_MODEL / 32), dim3(32, 8)>>>(W_qkv, p_wqt, D_MODEL, QKV_N);
    k_trT<<<dim3(D_MODEL / 32, D_MODEL / 32), dim3(32, 8)>>>(W_o, p_wot, D_MODEL, D_MODEL);

    k_gemm<true><<<dim3(QKV_N / 128, M_ROWS / 128), 256, GT_SMEM>>>(
        p_xh, p_wqt, b_qkv, p_qkv, QKV_N, D_MODEL);
    k_attn<<<dim3(B_SZ * NHEADS, S_LEN / 128), 256, AT_SMEM>>>();
    k_gemm<false><<<dim3(D_MODEL / 128, M_ROWS / 128), 256, GT_SMEM>>>(
        p_ctx, p_wot, b_o, out, D_MODEL, D_MODEL);
}

// round 17
// speedup vs baseline: 1.2490x; 1.0363x over previous
#include <cuda_runtime.h>
#include <cuda_fp16.h>
#include <cstdint>

#define B_SZ    2
#define S_LEN   2048
#define D_MODEL 1024
#define NHEADS  16
#define DK      64
#define M_ROWS  (B_SZ * S_LEN)     // 4096
#define QKV_N   (3 * D_MODEL)      // 3072

// Scratch (alloc-free: __device__ globals), all fp16 operands
__device__ __half g_qkv[(size_t)M_ROWS * QKV_N];     // qkv (token-major)
__device__ __half g_ctx[(size_t)M_ROWS * D_MODEL];   // ctx head-interleaved
__device__ __half g_xh [(size_t)M_ROWS * D_MODEL];   // x -> half
__device__ __half g_wqt[(size_t)QKV_N * D_MODEL];    // W_qkv^T [N][K] half
__device__ __half g_wot[(size_t)D_MODEL * D_MODEL];  // W_o^T  [N][K] half

// ---------------------------------------------------------------------------
// helpers
// ---------------------------------------------------------------------------
__device__ __forceinline__ uint32_t smem_u32(const void* p) {
    uint32_t a;
    asm("{ .reg .u64 t; cvta.to.shared.u64 t, %1; cvt.u32.u64 %0, t; }"
        : "=r"(a) : "l"(p));
    return a;
}

#define CP_ASYNC16(dst, src) \
    asm volatile("cp.async.cg.shared.global [%0], [%1], 16;" :: "r"(dst), "l"(src))
#define CP_COMMIT() asm volatile("cp.async.commit_group;" ::: "memory")
#define CP_WAIT1()  asm volatile("cp.async.wait_group 1;" ::: "memory")
#define CP_WAIT2()  asm volatile("cp.async.wait_group 2;" ::: "memory")

#define LDSM_X4(r0, r1, r2, r3, addr) \
    asm volatile("ldmatrix.sync.aligned.m8n8.x4.shared.b16 {%0,%1,%2,%3}, [%4];" \
                 : "=r"(r0), "=r"(r1), "=r"(r2), "=r"(r3) : "r"(addr))

#define LDSM_X4_T(r0, r1, r2, r3, addr) \
    asm volatile("ldmatrix.sync.aligned.m8n8.x4.trans.shared.b16 {%0,%1,%2,%3}, [%4];" \
                 : "=r"(r0), "=r"(r1), "=r"(r2), "=r"(r3) : "r"(addr))

// D(f32) += A(f16) * B(f16): m16n8k16
__device__ __forceinline__ void mma_f16(float* c, const unsigned* a,
                                        unsigned b0, unsigned b1) {
    asm volatile(
        "mma.sync.aligned.m16n8k16.row.col.f32.f16.f16.f32 "
        "{%0,%1,%2,%3}, {%4,%5,%6,%7}, {%8,%9}, {%0,%1,%2,%3};\n"
        : "+f"(c[0]), "+f"(c[1]), "+f"(c[2]), "+f"(c[3])
        : "r"(a[0]), "r"(a[1]), "r"(a[2]), "r"(a[3]), "r"(b0), "r"(b1));
}

__device__ __forceinline__ unsigned h2u(__half2 h) {
    return *reinterpret_cast<unsigned*>(&h);
}

// ---------------------------------------------------------------------------
// fused prep kernel: one launch does
//   task 0: x f32 -> half              (blocks [0, 4096))
//   task 1: W_qkv transpose -> g_wqt   (blocks [4096, 4096+3072))
//   task 2: W_o   transpose -> g_wot   (blocks [7168, 7168+1024))
// ---------------------------------------------------------------------------
#define PREP_X_BLKS   (M_ROWS * D_MODEL / 4 / 256)        // 4096
#define PREP_WQ_BLKS  ((QKV_N / 32) * (D_MODEL / 32))     // 3072
#define PREP_WO_BLKS  ((D_MODEL / 32) * (D_MODEL / 32))   // 1024
#define PREP_BLKS     (PREP_X_BLKS + PREP_WQ_BLKS + PREP_WO_BLKS)

__device__ __forceinline__ void trT_tile(const float* __restrict__ in,
                                         __half* __restrict__ out,
                                         int R, int C, int bx, int by,
                                         float (*tile)[33],
                                         int tx, int ty)
{
    const int c0 = bx * 32, r0 = by * 32;
    #pragma unroll
    for (int i = 0; i < 32; i += 8)
        tile[ty + i][tx] = in[(size_t)(r0 + ty + i) * C + c0 + tx];
    __syncthreads();
    #pragma unroll
    for (int i = 0; i < 32; i += 8)
        out[(size_t)(c0 + ty + i) * R + r0 + tx] = __float2half_rn(tile[tx][ty + i]);
}

__global__ void __launch_bounds__(256)
k_prep(const float* __restrict__ x, const float* __restrict__ Wq,
       const float* __restrict__ Wo)
{
    __shared__ float tile[32][33];
    const int tx = threadIdx.x, ty = threadIdx.y;
    const int bid = blockIdx.x;

    if (bid < PREP_X_BLKS) {
        const int i = bid * 256 + ty * 32 + tx;
        float4 v = ((const float4*)x)[i];
        ((__half2*)g_xh)[2 * i]     = __floats2half2_rn(v.x, v.y);
        ((__half2*)g_xh)[2 * i + 1] = __floats2half2_rn(v.z, v.w);
    } else if (bid < PREP_X_BLKS + PREP_WQ_BLKS) {
        const int b2 = bid - PREP_X_BLKS;
        trT_tile(Wq, g_wqt, D_MODEL, QKV_N, b2 % (QKV_N / 32), b2 / (QKV_N / 32),
                 tile, tx, ty);
    } else {
        const int b3 = bid - PREP_X_BLKS - PREP_WQ_BLKS;
        trT_tile(Wo, g_wot, D_MODEL, D_MODEL, b3 % (D_MODEL / 32), b3 / (D_MODEL / 32),
                 tile, tx, ty);
    }
}

// ---------------------------------------------------------------------------
// FP16 GEMM: C[M,N] = A[M,K] @ BT[N,K]^T + bias[N]
// Round-11 measured-best config: Block 128x128, BK=32, 4-stage cp.async,
// wait_group 2, 256 threads = 8 warps (4M x 2N), warp tile 32x64,
// mma m16n8k16, 2 CTAs/SM, stride 40 halfs, issue AFTER compute.
// ---------------------------------------------------------------------------
#define HS 40
#define STG_H (128 * HS)                 // halfs per operand per stage: 5120
#define ABUF(s) ((s) * 2 * STG_H)
#define BBUF(s) ((s) * 2 * STG_H + STG_H)
#define GT_SMEM (4 * 2 * STG_H * 2)      // 81920 B

template <bool HALF_OUT>
__global__ void __launch_bounds__(256, 2)
k_gemm(const __half* __restrict__ A, const __half* __restrict__ BT,
       const float* __restrict__ bias, void* __restrict__ Cv,
       int N, int K)
{
    extern __shared__ __half smh[];
    const uint32_t sb = smem_u32(smh);
    const int tid  = threadIdx.x;
    const int wid  = tid >> 5;
    const int lane = tid & 31;
    const int lr   = lane >> 2;
    const int lc   = lane & 3;
    const int wm   = (wid & 3) * 32;
    const int wn   = (wid >> 2) * 64;
    const int bm   = blockIdx.y * 128;
    const int bn   = blockIdx.x * 128;

    float acc[2][8][4];
    #pragma unroll
    for (int i = 0; i < 2; i++)
        #pragma unroll
        for (int j = 0; j < 8; j++)
            #pragma unroll
            for (int q = 0; q < 4; q++) acc[i][j][q] = 0.f;

    // cp.async: 512 16B-chunks per operand per stage -> 2 per thread each
    const int ldRow = tid >> 1;            // 0..127
    const int ldCol = (tid & 1) * 16;      // half col 0 or 16

    auto issue = [&](int t) {
        const int s  = t & 3;
        const int k0 = t * 32;
        const __half* ap = A  + (size_t)(bm + ldRow) * K + k0 + ldCol;
        const __half* bp = BT + (size_t)(bn + ldRow) * K + k0 + ldCol;
        const uint32_t da = sb + (ABUF(s) + ldRow * HS + ldCol) * 2;
        const uint32_t db = sb + (BBUF(s) + ldRow * HS + ldCol) * 2;
        CP_ASYNC16(da,      ap);
        CP_ASYNC16(da + 16, ap + 8);
        CP_ASYNC16(db,      bp);
        CP_ASYNC16(db + 16, bp + 8);
    };

    const int lane16 = lane & 15;
    const int lhi    = (lane >> 4) * 8;    // +8 halfs for second k-chunk

    const int nT = K / 32;
    issue(0); CP_COMMIT();
    issue(1); CP_COMMIT();
    issue(2); CP_COMMIT();

    for (int t = 0; t < nT; t++) {
        CP_WAIT2();
        __syncthreads();
        const int s = t & 3;
        const uint32_t aBase = sb + ABUF(s) * 2;
        const uint32_t bBase = sb + BBUF(s) * 2;

        #pragma unroll
        for (int kk = 0; kk < 2; kk++) {      // two k16 steps
            unsigned af0[4], af1[4];
            LDSM_X4(af0[0], af0[1], af0[2], af0[3],
                    aBase + ((wm + lane16) * HS + lhi + 16 * kk) * 2);
            LDSM_X4(af1[0], af1[1], af1[2], af1[3],
                    aBase + ((wm + 16 + lane16) * HS + lhi + 16 * kk) * 2);
            #pragma unroll
            for (int p = 0; p < 4; p++) {     // 16-n groups
                unsigned bf[4];
                LDSM_X4(bf[0], bf[1], bf[2], bf[3],
                        bBase + ((wn + 16 * p + lane16) * HS + lhi + 16 * kk) * 2);
                mma_f16(acc[0][2 * p],     af0, bf[0], bf[2]);
                mma_f16(acc[1][2 * p],     af1, bf[0], bf[2]);
                mma_f16(acc[0][2 * p + 1], af0, bf[1], bf[3]);
                mma_f16(acc[1][2 * p + 1], af1, bf[1], bf[3]);
            }
        }
        if (t + 3 < nT) issue(t + 3);
        CP_COMMIT();
    }

    #pragma unroll
    for (int j = 0; j < 8; j++) {
        const int col = bn + wn + 8 * j + 2 * lc;
        const float bs0 = bias[col], bs1 = bias[col + 1];
        #pragma unroll
        for (int i = 0; i < 2; i++) {
            const int row = bm + wm + 16 * i + lr;
            if (HALF_OUT) {
                __half* Ch = (__half*)Cv;
                *(__half2*)(Ch + (size_t)row * N + col) =
                    __floats2half2_rn(acc[i][j][0] + bs0, acc[i][j][1] + bs1);
                *(__half2*)(Ch + (size_t)(row + 8) * N + col) =
                    __floats2half2_rn(acc[i][j][2] + bs0, acc[i][j][3] + bs1);
            } else {
                float* Cf = (float*)Cv;
                *(float2*)(Cf + (size_t)row * N + col) =
                    make_float2(acc[i][j][0] + bs0, acc[i][j][1] + bs1);
                *(float2*)(Cf + (size_t)(row + 8) * N + col) =
                    make_float2(acc[i][j][2] + bs0, acc[i][j][3] + bs1);
            }
        }
    }
}

// ---------------------------------------------------------------------------
// FP16 flash attention: 256 threads (8 warps) = 128 q-rows, 64-key tiles.
// 3-stage cp.async (wait_group 1), 2 CTAs/SM, mma m16n8k16.
// P register-resident; V token-major, PV B-frags via ldmatrix.x4.trans.
// NEW: log2e folded into Q scale; softmax uses exp2f (EX2 only, no FMUL).
// ---------------------------------------------------------------------------
#define AHS 72
#define KSTG (64 * AHS)                            // 4608 halfs
#define KOFF(s) ((s) * 2 * KSTG)
#define VOFF(s) ((s) * 2 * KSTG + KSTG)
#define AT_SMEM (3 * 2 * KSTG * 2)                 // 55296 B

__global__ void __launch_bounds__(256, 2)
k_attn()
{
    extern __shared__ __half smh[];
    const uint32_t sb = smem_u32(smh);
    const int tid  = threadIdx.x;
    const int wid  = tid >> 5;
    const int lane = tid & 31;
    const int lr   = lane >> 2;
    const int lc   = lane & 3;
    const int bh   = blockIdx.x;
    const int b    = bh >> 4;
    const int h    = bh & 15;
    const int q0   = blockIdx.y * 128;

    const __half* base = g_qkv + (size_t)b * S_LEN * QKV_N;
    const int ho = h * (3 * DK);

    // Q fragments from gmem, scaled by 0.125 * log2(e): scores in log2 domain
    unsigned Qf[4][4];
    {
        const __half2 scl = __float2half2_rn(0.125f * 1.4426950408889634f);
        const __half* qr0 = base + (size_t)(q0 + wid * 16 + lr) * QKV_N + ho;
        const __half* qr1 = qr0 + (size_t)8 * QKV_N;
        #pragma unroll
        for (int kk = 0; kk < 4; kk++) {
            Qf[kk][0] = h2u(__hmul2(*(const __half2*)(qr0 + 16 * kk + 2 * lc), scl));
            Qf[kk][1] = h2u(__hmul2(*(const __half2*)(qr1 + 16 * kk + 2 * lc), scl));
            Qf[kk][2] = h2u(__hmul2(*(const __half2*)(qr0 + 16 * kk + 2 * lc + 8), scl));
            Qf[kk][3] = h2u(__hmul2(*(const __half2*)(qr1 + 16 * kk + 2 * lc + 8), scl));
        }
    }

    // cp.async: K and V each 64 rows (keys) x 8 chunks; 2 chunks/thread each.
    auto issue = [&](int t) {
        const int s  = t % 3;
        const int r  = tid >> 2;            // key row 0..63
        const int cb = (tid & 3) * 16;      // half col 0/16/32/48
        const __half* kp = base + (size_t)(t * 64 + r) * QKV_N + ho + DK + cb;
        const uint32_t dk_ = sb + (KOFF(s) + r * AHS + cb) * 2;
        CP_ASYNC16(dk_,      kp);
        CP_ASYNC16(dk_ + 16, kp + 8);
        const uint32_t dv = sb + (VOFF(s) + r * AHS + cb) * 2;
        CP_ASYNC16(dv,      kp + DK);
        CP_ASYNC16(dv + 16, kp + DK + 8);
    };

    float oAcc[8][4];
    #pragma unroll
    for (int j = 0; j < 8; j++)
        #pragma unroll
        for (int q = 0; q < 4; q++) oAcc[j][q] = 0.f;
    float m0 = -1e30f, m1 = -1e30f, l0 = 0.f, l1 = 0.f;

    const int lane16 = lane & 15;
    const int lhi    = (lane >> 4) * 8;
    const int vrow = (lane & 7) + ((lane >> 4) << 3);
    const int vcol = ((lane >> 3) & 1) << 3;

    const int nT = S_LEN / 64;
    issue(0); CP_COMMIT();
    issue(1); CP_COMMIT();

    for (int t = 0; t < nT; t++) {
        CP_WAIT1();
        __syncthreads();
        // stage (t+2)%3 == (t-1)%3 freed by the barrier above
        if (t + 2 < nT) issue(t + 2);
        CP_COMMIT();

        const int s = t % 3;
        const uint32_t kBase = sb + KOFF(s) * 2;
        const uint32_t vBase = sb + VOFF(s) * 2;

        // S = Q @ K^T  (16 q x 64 keys per warp), scores in log2 units
        float sAcc[8][4];
        #pragma unroll
        for (int j = 0; j < 8; j++)
            sAcc[j][0] = sAcc[j][1] = sAcc[j][2] = sAcc[j][3] = 0.f;
        #pragma unroll
        for (int kk = 0; kk < 4; kk++) {
            #pragma unroll
            for (int p = 0; p < 4; p++) {
                unsigned bf[4];
                LDSM_X4(bf[0], bf[1], bf[2], bf[3],
                        kBase + ((16 * p + lane16) * AHS + lhi + 16 * kk) * 2);
                mma_f16(sAcc[2 * p],     Qf[kk], bf[0], bf[2]);
                mma_f16(sAcc[2 * p + 1], Qf[kk], bf[1], bf[3]);
            }
        }

        // online softmax in log2 domain (rows lr and lr+8)
        float mx0 = -1e30f, mx1 = -1e30f;
        #pragma unroll
        for (int j = 0; j < 8; j++) {
            mx0 = fmaxf(mx0, fmaxf(sAcc[j][0], sAcc[j][1]));
            mx1 = fmaxf(mx1, fmaxf(sAcc[j][2], sAcc[j][3]));
        }
        mx0 = fmaxf(mx0, __shfl_xor_sync(0xffffffffu, mx0, 1));
        mx0 = fmaxf(mx0, __shfl_xor_sync(0xffffffffu, mx0, 2));
        mx1 = fmaxf(mx1, __shfl_xor_sync(0xffffffffu, mx1, 1));
        mx1 = fmaxf(mx1, __shfl_xor_sync(0xffffffffu, mx1, 2));

        const float mn0 = fmaxf(m0, mx0), mn1 = fmaxf(m1, mx1);
        const float cor0 = exp2f(m0 - mn0), cor1 = exp2f(m1 - mn1);
        m0 = mn0; m1 = mn1;

        float s0 = 0.f, s1 = 0.f;
        #pragma unroll
        for (int j = 0; j < 8; j++) {
            sAcc[j][0] = exp2f(sAcc[j][0] - mn0); s0 += sAcc[j][0];
            sAcc[j][1] = exp2f(sAcc[j][1] - mn0); s0 += sAcc[j][1];
            sAcc[j][2] = exp2f(sAcc[j][2] - mn1); s1 += sAcc[j][2];
            sAcc[j][3] = exp2f(sAcc[j][3] - mn1); s1 += sAcc[j][3];
        }
        s0 += __shfl_xor_sync(0xffffffffu, s0, 1);
        s0 += __shfl_xor_sync(0xffffffffu, s0, 2);
        s1 += __shfl_xor_sync(0xffffffffu, s1, 1);
        s1 += __shfl_xor_sync(0xffffffffu, s1, 2);
        l0 = l0 * cor0 + s0;
        l1 = l1 * cor1 + s1;

        #pragma unroll
        for (int j = 0; j < 8; j++) {
            oAcc[j][0] *= cor0; oAcc[j][1] *= cor0;
            oAcc[j][2] *= cor1; oAcc[j][3] *= cor1;
        }

        // O += P @ V: P A-frags from sAcc registers; V B-frags via x4.trans
        #pragma unroll
        for (int kk = 0; kk < 4; kk++) {      // 16-key steps
            unsigned pf[4];
            pf[0] = h2u(__floats2half2_rn(sAcc[2 * kk][0],     sAcc[2 * kk][1]));
            pf[1] = h2u(__floats2half2_rn(sAcc[2 * kk][2],     sAcc[2 * kk][3]));
            pf[2] = h2u(__floats2half2_rn(sAcc[2 * kk + 1][0], sAcc[2 * kk + 1][1]));
            pf[3] = h2u(__floats2half2_rn(sAcc[2 * kk + 1][2], sAcc[2 * kk + 1][3]));
            #pragma unroll
            for (int p = 0; p < 4; p++) {     // 16-d groups
                unsigned bf[4];
                LDSM_X4_T(bf[0], bf[1], bf[2], bf[3],
                          vBase + ((16 * kk + vrow) * AHS + 16 * p + vcol) * 2);
                mma_f16(oAcc[2 * p],     pf, bf[0], bf[2]);
                mma_f16(oAcc[2 * p + 1], pf, bf[1], bf[3]);
            }
        }
    }

    // epilogue: normalize, convert half, store head-interleaved ctx
    const float inv0 = 1.f / l0, inv1 = 1.f / l1;
    __half* orow0 = g_ctx + (size_t)(b * S_LEN + q0 + wid * 16 + lr) * D_MODEL + h * DK;
    __half* orow1 = orow0 + (size_t)8 * D_MODEL;
    #pragma unroll
    for (int j = 0; j < 8; j++) {
        const int colo = 8 * j + 2 * lc;
        *(__half2*)(orow0 + colo) =
            __floats2half2_rn(oAcc[j][0] * inv0, oAcc[j][1] * inv0);
        *(__half2*)(orow1 + colo) =
            __floats2half2_rn(oAcc[j][2] * inv1, oAcc[j][3] * inv1);
    }
}

// ---------------------------------------------------------------------------
extern "C" void kernel_launch(void* const* d_in, const int* in_sizes, int n_in,
                              void* d_out, int out_size)
{
    (void)in_sizes; (void)n_in; (void)out_size;
    const float* x     = (const float*)d_in[0];
    const float* W_qkv = (const float*)d_in[1];
    const float* b_qkv = (const float*)d_in[2];
    const float* W_o   = (const float*)d_in[3];
    const float* b_o   = (const float*)d_in[4];
    float* out = (float*)d_out;

    static __half *p_qkv = nullptr, *p_ctx, *p_xh, *p_wqt, *p_wot;
    if (!p_qkv) {
        cudaGetSymbolAddress((void**)&p_qkv, g_qkv);
        cudaGetSymbolAddress((void**)&p_ctx, g_ctx);
        cudaGetSymbolAddress((void**)&p_xh,  g_xh);
        cudaGetSymbolAddress((void**)&p_wqt, g_wqt);
        cudaGetSymbolAddress((void**)&p_wot, g_wot);
        cudaFuncSetAttribute(k_gemm<true>,
                             cudaFuncAttributeMaxDynamicSharedMemorySize, GT_SMEM);
        cudaFuncSetAttribute(k_gemm<false>,
                             cudaFuncAttributeMaxDynamicSharedMemorySize, GT_SMEM);
        cudaFuncSetAttribute(k_attn,
                             cudaFuncAttributeMaxDynamicSharedMemorySize, AT_SMEM);
    }

    // fused prep: x -> half; both weights -> transposed half (one launch)
    k_prep<<<PREP_BLKS, dim3(32, 8)>>>(x, W_qkv, W_o);

    k_gemm<true><<<dim3(QKV_N / 128, M_ROWS / 128), 256, GT_SMEM>>>(
        p_xh, p_wqt, b_qkv, p_qkv, QKV_N, D_MODEL);
    k_attn<<<dim3(B_SZ * NHEADS, S_LEN / 128), 256, AT_SMEM>>>();
    k_gemm<false><<<dim3(D_MODEL / 128, M_ROWS / 128), 256, GT_SMEM>>>(
        p_ctx, p_wot, b_o, out, D_MODEL, D_MODEL);
}